// round 2
// baseline (speedup 1.0000x reference)
#include <cuda_runtime.h>
#include <cuda_bf16.h>

#define DD     16
#define NHEAD  8
#define LAYERS 8
#define FFD    16
#define KW     35
#define SEQIN  3500
#define NP     100
#define SS     101
#define HSTR   17      // padded row stride (odd -> no smem bank conflicts)
#define NT     128     // threads per block

__global__ __launch_bounds__(NT) void TorrinE0_fused_kernel(
    const float* __restrict__ x,      const float* __restrict__ conv_w, const float* __restrict__ conv_b,
    const float* __restrict__ cls_emb,const float* __restrict__ Wqkv,   const float* __restrict__ bqkv,
    const float* __restrict__ Wo,     const float* __restrict__ bo,
    const float* __restrict__ W1,     const float* __restrict__ b1,
    const float* __restrict__ W2,     const float* __restrict__ b2,
    const float* __restrict__ ln1_g,  const float* __restrict__ ln1_b,
    const float* __restrict__ ln2_g,  const float* __restrict__ ln2_b,
    const float* __restrict__ lnf_g,  const float* __restrict__ lnf_b,
    const float* __restrict__ end_w,  const float* __restrict__ end_b,
    const float* __restrict__ head_w, const float* __restrict__ head_b,
    float* __restrict__ out)
{
    __shared__ float s_h  [SS * HSTR];
    __shared__ __align__(16) float s_qkv[SS * 48];  // also holds x (3500 <= 4848) during conv
    __shared__ float s_ctx[SS * HSTR];
    __shared__ float s_ff [SS * HSTR];
    __shared__ float s_Wqkv[768];        // also holds conv_w (560) during conv
    __shared__ float s_bqkv[48];
    __shared__ float s_Wo[256], s_W1[256], s_W2[256];
    __shared__ float s_bo[16],  s_b1[16], s_b2[16];
    __shared__ float s_ln[64];           // ln1_g, ln1_b, ln2_g, ln2_b

    const int tid = threadIdx.x;
    const int b   = blockIdx.x;

    // ---------- stage x row + conv weights ----------
    for (int i = tid; i < SEQIN; i += NT) s_qkv[i] = x[(size_t)b * SEQIN + i];
    for (int i = tid; i < DD * KW; i += NT) s_Wqkv[i] = conv_w[i];
    if (tid < DD) s_bqkv[tid] = conv_b[tid];
    __syncthreads();

    // ---------- conv patch embedding: h[p+1][f] ----------
    for (int idx = tid; idx < NP * DD; idx += NT) {
        int p = idx >> 4, f = idx & 15;
        float acc = s_bqkv[f];
        const float* xp = &s_qkv[p * KW];
        const float* wf = &s_Wqkv[f * KW];
        #pragma unroll
        for (int k = 0; k < KW; k++) acc = fmaf(xp[k], wf[k], acc);
        s_h[(p + 1) * HSTR + f] = acc;
    }
    if (tid < DD) s_h[tid] = cls_emb[tid];
    __syncthreads();

    const float scale = 0.70710678118654752f; // 1/sqrt(D/H = 2)

    // ---------- transformer layers ----------
    for (int l = 0; l < LAYERS; l++) {
        // stage this layer's weights into smem
        for (int i = tid; i < 768; i += NT) s_Wqkv[i] = Wqkv[l * 768 + i];
        for (int i = tid; i < 256; i += NT) {
            s_Wo[i] = Wo[l * 256 + i];
            s_W1[i] = W1[l * 256 + i];
            s_W2[i] = W2[l * 256 + i];
        }
        if (tid < 48) s_bqkv[tid] = bqkv[l * 48 + tid];
        if (tid < 16) {
            s_bo[tid]      = bo[l * 16 + tid];
            s_b1[tid]      = b1[l * 16 + tid];
            s_b2[tid]      = b2[l * 16 + tid];
            s_ln[tid]      = ln1_g[l * 16 + tid];
            s_ln[16 + tid] = ln1_b[l * 16 + tid];
            s_ln[32 + tid] = ln2_g[l * 16 + tid];
            s_ln[48 + tid] = ln2_b[l * 16 + tid];
        }
        __syncthreads();

        // ---- QKV projection: qkv[s][e] = h[s] . Wqkv[e] + b ----
        for (int idx = tid; idx < SS * 48; idx += NT) {
            int s = idx / 48, e = idx - s * 48;
            const float* hr = &s_h[s * HSTR];
            const float* wr = &s_Wqkv[e * 16];
            float acc = s_bqkv[e];
            #pragma unroll
            for (int d = 0; d < 16; d++) acc = fmaf(hr[d], wr[d], acc);
            s_qkv[idx] = acc;
        }
        __syncthreads();

        // ---- attention: one (head, s) pair per thread-iteration ----
        const float2* qkv2 = reinterpret_cast<const float2*>(s_qkv);
        for (int pair = tid; pair < NHEAD * SS; pair += NT) {
            int hh = pair / SS;
            int s  = pair - hh * SS;
            float2 q = qkv2[s * 24 + hh];
            // pass 1: max score
            float m = -1e30f;
            #pragma unroll 4
            for (int t = 0; t < SS; t++) {
                float2 k = qkv2[t * 24 + 8 + hh];
                float sc = (q.x * k.x + q.y * k.y) * scale;
                m = fmaxf(m, sc);
            }
            // pass 2: exp-sum + weighted V accumulation
            float den = 0.f, c0 = 0.f, c1 = 0.f;
            #pragma unroll 4
            for (int t = 0; t < SS; t++) {
                float2 k = qkv2[t * 24 + 8 + hh];
                float2 v = qkv2[t * 24 + 16 + hh];
                float sc = (q.x * k.x + q.y * k.y) * scale;
                float e  = __expf(sc - m);
                den += e;
                c0 = fmaf(e, v.x, c0);
                c1 = fmaf(e, v.y, c1);
            }
            float inv = __frcp_rn(den);
            s_ctx[s * HSTR + hh * 2]     = c0 * inv;
            s_ctx[s * HSTR + hh * 2 + 1] = c1 * inv;
        }
        __syncthreads();

        // ---- Wo + residual + LN1 (one row per thread) ----
        if (tid < SS) {
            int s = tid;
            float vv[16];
            float cr[16];
            #pragma unroll
            for (int d = 0; d < 16; d++) cr[d] = s_ctx[s * HSTR + d];
            #pragma unroll
            for (int o = 0; o < 16; o++) {
                float acc = s_bo[o];
                const float* wr = &s_Wo[o * 16];
                #pragma unroll
                for (int d = 0; d < 16; d++) acc = fmaf(cr[d], wr[d], acc);
                vv[o] = s_h[s * HSTR + o] + acc;
            }
            float mu = 0.f;
            #pragma unroll
            for (int d = 0; d < 16; d++) mu += vv[d];
            mu *= 0.0625f;
            float var = 0.f;
            #pragma unroll
            for (int d = 0; d < 16; d++) { float t = vv[d] - mu; var = fmaf(t, t, var); }
            var *= 0.0625f;
            float r = rsqrtf(var + 1e-5f);
            #pragma unroll
            for (int d = 0; d < 16; d++)
                s_h[s * HSTR + d] = (vv[d] - mu) * r * s_ln[d] + s_ln[16 + d];
        }
        __syncthreads();

        // ---- FF1 + relu ----
        for (int idx = tid; idx < SS * FFD; idx += NT) {
            int s = idx >> 4, f = idx & 15;
            const float* hr = &s_h[s * HSTR];
            const float* wr = &s_W1[f * 16];
            float acc = s_b1[f];
            #pragma unroll
            for (int d = 0; d < 16; d++) acc = fmaf(hr[d], wr[d], acc);
            s_ff[s * HSTR + f] = fmaxf(acc, 0.f);
        }
        __syncthreads();

        // ---- FF2 + residual + LN2 (one row per thread) ----
        if (tid < SS) {
            int s = tid;
            float vv[16];
            float fr[16];
            #pragma unroll
            for (int f = 0; f < 16; f++) fr[f] = s_ff[s * HSTR + f];
            #pragma unroll
            for (int d = 0; d < 16; d++) {
                float acc = s_b2[d];
                const float* wr = &s_W2[d * 16];
                #pragma unroll
                for (int f = 0; f < 16; f++) acc = fmaf(fr[f], wr[f], acc);
                vv[d] = s_h[s * HSTR + d] + acc;
            }
            float mu = 0.f;
            #pragma unroll
            for (int d = 0; d < 16; d++) mu += vv[d];
            mu *= 0.0625f;
            float var = 0.f;
            #pragma unroll
            for (int d = 0; d < 16; d++) { float t = vv[d] - mu; var = fmaf(t, t, var); }
            var *= 0.0625f;
            float r = rsqrtf(var + 1e-5f);
            #pragma unroll
            for (int d = 0; d < 16; d++)
                s_h[s * HSTR + d] = (vv[d] - mu) * r * s_ln[32 + d] + s_ln[48 + d];
        }
        __syncthreads();
    }

    // ---------- final LN on cls row only ----------
    if (tid == 0) {
        float mu = 0.f;
        #pragma unroll
        for (int d = 0; d < 16; d++) mu += s_h[d];
        mu *= 0.0625f;
        float var = 0.f;
        #pragma unroll
        for (int d = 0; d < 16; d++) { float t = s_h[d] - mu; var = fmaf(t, t, var); }
        var *= 0.0625f;
        float r = rsqrtf(var + 1e-5f);
        #pragma unroll
        for (int d = 0; d < 16; d++)
            s_ctx[d] = (s_h[d] - mu) * r * lnf_g[d] + lnf_b[d];
    }
    __syncthreads();

    // ---------- end projection (fused with head weight) ----------
    if (tid < 100) {
        float acc = end_b[tid];
        #pragma unroll
        for (int d = 0; d < 16; d++) acc = fmaf(s_ctx[d], end_w[tid * 16 + d], acc);
        s_ff[tid] = acc * head_w[tid];
    }
    __syncthreads();

    // ---------- head sum + sigmoid ----------
    if (tid == 0) {
        float acc = head_b[0];
        #pragma unroll 4
        for (int j = 0; j < 100; j++) acc += s_ff[j];
        out[b] = 1.f / (1.f + __expf(-acc));
    }
}

extern "C" void kernel_launch(void* const* d_in, const int* in_sizes, int n_in,
                              void* d_out, int out_size) {
    const float* x       = (const float*)d_in[0];
    const float* conv_w  = (const float*)d_in[1];
    const float* conv_b  = (const float*)d_in[2];
    const float* cls_emb = (const float*)d_in[3];
    const float* Wqkv    = (const float*)d_in[4];
    const float* bqkv    = (const float*)d_in[5];
    const float* Wo      = (const float*)d_in[6];
    const float* bo      = (const float*)d_in[7];
    const float* W1      = (const float*)d_in[8];
    const float* b1      = (const float*)d_in[9];
    const float* W2      = (const float*)d_in[10];
    const float* b2      = (const float*)d_in[11];
    const float* ln1_g   = (const float*)d_in[12];
    const float* ln1_b   = (const float*)d_in[13];
    const float* ln2_g   = (const float*)d_in[14];
    const float* ln2_b   = (const float*)d_in[15];
    const float* lnf_g   = (const float*)d_in[16];
    const float* lnf_b   = (const float*)d_in[17];
    const float* end_w   = (const float*)d_in[18];
    const float* end_b   = (const float*)d_in[19];
    const float* head_w  = (const float*)d_in[20];
    const float* head_b  = (const float*)d_in[21];

    int B = in_sizes[0] / SEQIN;

    TorrinE0_fused_kernel<<<B, NT>>>(
        x, conv_w, conv_b, cls_emb, Wqkv, bqkv, Wo, bo, W1, b1, W2, b2,
        ln1_g, ln1_b, ln2_g, ln2_b, lnf_g, lnf_b, end_w, end_b, head_w, head_b,
        (float*)d_out);
}

// round 3
// speedup vs baseline: 2.2232x; 2.2232x over previous
#include <cuda_runtime.h>
#include <cuda_bf16.h>

#define DD     16
#define NHEAD  8
#define LAYERS 8
#define FFD    16
#define KW     35
#define SEQIN  3500
#define NP     100
#define SS     101
#define HSTR   20      // padded row stride, 16B-aligned rows (20 floats = 80B)
#define NT     128     // threads per block
#define QB     8       // query rows per attention task
#define NBLK   13      // ceil(SS/QB)

__device__ __forceinline__ float ex2f_fast(float x) {
    float y;
    asm("ex2.approx.ftz.f32 %0, %1;" : "=f"(y) : "f"(x));
    return y;
}

// 16-element dot product via float4 (both pointers 16B aligned)
__device__ __forceinline__ float dot16(const float4* __restrict__ a,
                                       const float4* __restrict__ b, float acc) {
    #pragma unroll
    for (int i = 0; i < 4; i++) {
        float4 u = a[i], v = b[i];
        acc = fmaf(u.x, v.x, acc);
        acc = fmaf(u.y, v.y, acc);
        acc = fmaf(u.z, v.z, acc);
        acc = fmaf(u.w, v.w, acc);
    }
    return acc;
}

__global__ __launch_bounds__(NT, 5) void TorrinE0_fused_kernel(
    const float* __restrict__ x,      const float* __restrict__ conv_w, const float* __restrict__ conv_b,
    const float* __restrict__ cls_emb,const float* __restrict__ Wqkv,   const float* __restrict__ bqkv,
    const float* __restrict__ Wo,     const float* __restrict__ bo,
    const float* __restrict__ W1,     const float* __restrict__ b1,
    const float* __restrict__ W2,     const float* __restrict__ b2,
    const float* __restrict__ ln1_g,  const float* __restrict__ ln1_b,
    const float* __restrict__ ln2_g,  const float* __restrict__ ln2_b,
    const float* __restrict__ lnf_g,  const float* __restrict__ lnf_b,
    const float* __restrict__ end_w,  const float* __restrict__ end_b,
    const float* __restrict__ head_w, const float* __restrict__ head_b,
    float* __restrict__ out)
{
    __shared__ __align__(16) float s_h  [SS * HSTR];
    __shared__ __align__(16) float s_qkv[SS * 48];   // also holds x (3500 <= 4848) during conv
    __shared__ __align__(16) float s_tmp[SS * HSTR]; // ctx during attn, ff during MLP
    __shared__ __align__(16) float s_Wqkv[768];      // also holds conv_w (560) during conv
    __shared__ __align__(16) float s_bqkv[48];
    __shared__ __align__(16) float s_Wo[256], s_W1[256], s_W2[256];
    __shared__ float s_bo[16],  s_b1[16], s_b2[16];
    __shared__ float s_ln[64];                       // ln1_g, ln1_b, ln2_g, ln2_b

    const int tid = threadIdx.x;
    const int b   = blockIdx.x;

    // ---------- stage x row (float4: 3500 = 875*4, rows 16B aligned) + conv weights ----------
    {
        const float4* x4 = reinterpret_cast<const float4*>(x + (size_t)b * SEQIN);
        float4* q4 = reinterpret_cast<float4*>(s_qkv);
        for (int i = tid; i < SEQIN / 4; i += NT) q4[i] = x4[i];
    }
    for (int i = tid; i < DD * KW; i += NT) s_Wqkv[i] = conv_w[i];
    if (tid < DD) s_bqkv[tid] = conv_b[tid];
    __syncthreads();

    // ---------- conv patch embedding: h[p+1][f] ----------
    for (int idx = tid; idx < NP * DD; idx += NT) {
        int p = idx >> 4, f = idx & 15;
        float acc = s_bqkv[f];
        const float* xp = &s_qkv[p * KW];
        const float* wf = &s_Wqkv[f * KW];
        #pragma unroll
        for (int k = 0; k < KW; k++) acc = fmaf(xp[k], wf[k], acc);
        s_h[(p + 1) * HSTR + f] = acc;
    }
    if (tid < DD) s_h[tid] = cls_emb[tid];
    __syncthreads();

    // q pre-scale folds softmax scale and log2(e): exp(s*scale) == 2^(s*scale*log2e)
    const float QSC = 1.44269504088896f * 0.707106781186547f;

    // ---------- transformer layers ----------
    for (int l = 0; l < LAYERS; l++) {
        // stage this layer's weights into smem
        for (int i = tid; i < 768; i += NT) s_Wqkv[i] = Wqkv[l * 768 + i];
        for (int i = tid; i < 256; i += NT) {
            s_Wo[i] = Wo[l * 256 + i];
            s_W1[i] = W1[l * 256 + i];
            s_W2[i] = W2[l * 256 + i];
        }
        if (tid < 48) s_bqkv[tid] = bqkv[l * 48 + tid];
        if (tid < 16) {
            s_bo[tid]      = bo[l * 16 + tid];
            s_b1[tid]      = b1[l * 16 + tid];
            s_b2[tid]      = b2[l * 16 + tid];
            s_ln[tid]      = ln1_g[l * 16 + tid];
            s_ln[16 + tid] = ln1_b[l * 16 + tid];
            s_ln[32 + tid] = ln2_g[l * 16 + tid];
            s_ln[48 + tid] = ln2_b[l * 16 + tid];
        }
        __syncthreads();

        // ---- QKV projection (float4 dots) ----
        {
            const float4* w4base = reinterpret_cast<const float4*>(s_Wqkv);
            for (int idx = tid; idx < SS * 48; idx += NT) {
                int s = idx / 48, e = idx - s * 48;
                const float4* h4 = reinterpret_cast<const float4*>(&s_h[s * HSTR]);
                s_qkv[idx] = dot16(h4, w4base + e * 4, s_bqkv[e]);
            }
        }
        __syncthreads();

        // ---- attention: single-pass softmax, QB query rows per task ----
        {
            const float2* qkv2 = reinterpret_cast<const float2*>(s_qkv);
            if (tid < NHEAD * NBLK) {
                int hh = tid / NBLK;
                int s0 = (tid - hh * NBLK) * QB;

                float2 q[QB];
                #pragma unroll
                for (int i = 0; i < QB; i++) {
                    int s = s0 + i;
                    if (s < SS) {
                        float2 t = qkv2[s * 24 + hh];
                        q[i].x = t.x * QSC; q[i].y = t.y * QSC;
                    } else {
                        q[i].x = 0.f; q[i].y = 0.f;
                    }
                }
                float den[QB], cx[QB], cy[QB];
                #pragma unroll
                for (int i = 0; i < QB; i++) { den[i] = 0.f; cx[i] = 0.f; cy[i] = 0.f; }

                for (int t = 0; t < SS; t++) {
                    float2 k = qkv2[t * 24 + 8  + hh];
                    float2 v = qkv2[t * 24 + 16 + hh];
                    #pragma unroll
                    for (int i = 0; i < QB; i++) {
                        float sc = fmaf(q[i].y, k.y, q[i].x * k.x);
                        float e  = ex2f_fast(sc);
                        den[i] += e;
                        cx[i] = fmaf(e, v.x, cx[i]);
                        cy[i] = fmaf(e, v.y, cy[i]);
                    }
                }
                #pragma unroll
                for (int i = 0; i < QB; i++) {
                    int s = s0 + i;
                    if (s < SS) {
                        float inv = __frcp_rn(den[i]);
                        float2 o; o.x = cx[i] * inv; o.y = cy[i] * inv;
                        *reinterpret_cast<float2*>(&s_tmp[s * HSTR + hh * 2]) = o;
                    }
                }
            }
        }
        __syncthreads();

        // ---- Wo + residual + LN1 (one row per thread) ----
        if (tid < SS) {
            const float4* c4 = reinterpret_cast<const float4*>(&s_tmp[tid * HSTR]);
            const float4* h4 = reinterpret_cast<const float4*>(&s_h[tid * HSTR]);
            const float4* w4 = reinterpret_cast<const float4*>(s_Wo);
            float4 cr[4] = {c4[0], c4[1], c4[2], c4[3]};
            float vv[16];
            #pragma unroll
            for (int o = 0; o < 16; o++)
                vv[o] = dot16(cr, w4 + o * 4, s_bo[o]);
            float4 hr[4] = {h4[0], h4[1], h4[2], h4[3]};
            const float* hs = reinterpret_cast<const float*>(hr);
            float mu = 0.f;
            #pragma unroll
            for (int d = 0; d < 16; d++) { vv[d] += hs[d]; mu += vv[d]; }
            mu *= 0.0625f;
            float var = 0.f;
            #pragma unroll
            for (int d = 0; d < 16; d++) { float t = vv[d] - mu; var = fmaf(t, t, var); }
            float r = rsqrtf(fmaf(var, 0.0625f, 1e-5f));
            float4 ov[4];
            float* os = reinterpret_cast<float*>(ov);
            #pragma unroll
            for (int d = 0; d < 16; d++)
                os[d] = (vv[d] - mu) * r * s_ln[d] + s_ln[16 + d];
            float4* oh = reinterpret_cast<float4*>(&s_h[tid * HSTR]);
            oh[0] = ov[0]; oh[1] = ov[1]; oh[2] = ov[2]; oh[3] = ov[3];
        }
        __syncthreads();

        // ---- FF1 + relu (float4 dots) ----
        {
            const float4* w4 = reinterpret_cast<const float4*>(s_W1);
            for (int idx = tid; idx < SS * FFD; idx += NT) {
                int s = idx >> 4, f = idx & 15;
                const float4* h4 = reinterpret_cast<const float4*>(&s_h[s * HSTR]);
                float acc = dot16(h4, w4 + f * 4, s_b1[f]);
                s_tmp[s * HSTR + f] = fmaxf(acc, 0.f);
            }
        }
        __syncthreads();

        // ---- FF2 + residual + LN2 (one row per thread) ----
        if (tid < SS) {
            const float4* f4 = reinterpret_cast<const float4*>(&s_tmp[tid * HSTR]);
            const float4* h4 = reinterpret_cast<const float4*>(&s_h[tid * HSTR]);
            const float4* w4 = reinterpret_cast<const float4*>(s_W2);
            float4 fr[4] = {f4[0], f4[1], f4[2], f4[3]};
            float vv[16];
            #pragma unroll
            for (int d = 0; d < 16; d++)
                vv[d] = dot16(fr, w4 + d * 4, s_b2[d]);
            float4 hr[4] = {h4[0], h4[1], h4[2], h4[3]};
            const float* hs = reinterpret_cast<const float*>(hr);
            float mu = 0.f;
            #pragma unroll
            for (int d = 0; d < 16; d++) { vv[d] += hs[d]; mu += vv[d]; }
            mu *= 0.0625f;
            float var = 0.f;
            #pragma unroll
            for (int d = 0; d < 16; d++) { float t = vv[d] - mu; var = fmaf(t, t, var); }
            float r = rsqrtf(fmaf(var, 0.0625f, 1e-5f));
            float4 ov[4];
            float* os = reinterpret_cast<float*>(ov);
            #pragma unroll
            for (int d = 0; d < 16; d++)
                os[d] = (vv[d] - mu) * r * s_ln[32 + d] + s_ln[48 + d];
            float4* oh = reinterpret_cast<float4*>(&s_h[tid * HSTR]);
            oh[0] = ov[0]; oh[1] = ov[1]; oh[2] = ov[2]; oh[3] = ov[3];
        }
        __syncthreads();
    }

    // ---------- final LN on cls row only ----------
    if (tid == 0) {
        float mu = 0.f;
        #pragma unroll
        for (int d = 0; d < 16; d++) mu += s_h[d];
        mu *= 0.0625f;
        float var = 0.f;
        #pragma unroll
        for (int d = 0; d < 16; d++) { float t = s_h[d] - mu; var = fmaf(t, t, var); }
        float r = rsqrtf(fmaf(var, 0.0625f, 1e-5f));
        #pragma unroll
        for (int d = 0; d < 16; d++)
            s_tmp[d] = (s_h[d] - mu) * r * lnf_g[d] + lnf_b[d];
    }
    __syncthreads();

    // ---------- end projection (fused with head weight) ----------
    if (tid < 100) {
        float acc = end_b[tid];
        #pragma unroll
        for (int d = 0; d < 16; d++) acc = fmaf(s_tmp[d], end_w[tid * 16 + d], acc);
        s_tmp[HSTR + tid] = acc * head_w[tid];   // park past the cls row
    }
    __syncthreads();

    // ---------- head sum + sigmoid ----------
    if (tid == 0) {
        float acc = head_b[0];
        #pragma unroll 4
        for (int j = 0; j < 100; j++) acc += s_tmp[HSTR + j];
        out[b] = 1.f / (1.f + ex2f_fast(-acc * 1.44269504088896f));
    }
}

extern "C" void kernel_launch(void* const* d_in, const int* in_sizes, int n_in,
                              void* d_out, int out_size) {
    const float* x       = (const float*)d_in[0];
    const float* conv_w  = (const float*)d_in[1];
    const float* conv_b  = (const float*)d_in[2];
    const float* cls_emb = (const float*)d_in[3];
    const float* Wqkv    = (const float*)d_in[4];
    const float* bqkv    = (const float*)d_in[5];
    const float* Wo      = (const float*)d_in[6];
    const float* bo      = (const float*)d_in[7];
    const float* W1      = (const float*)d_in[8];
    const float* b1      = (const float*)d_in[9];
    const float* W2      = (const float*)d_in[10];
    const float* b2      = (const float*)d_in[11];
    const float* ln1_g   = (const float*)d_in[12];
    const float* ln1_b   = (const float*)d_in[13];
    const float* ln2_g   = (const float*)d_in[14];
    const float* ln2_b   = (const float*)d_in[15];
    const float* lnf_g   = (const float*)d_in[16];
    const float* lnf_b   = (const float*)d_in[17];
    const float* end_w   = (const float*)d_in[18];
    const float* end_b   = (const float*)d_in[19];
    const float* head_w  = (const float*)d_in[20];
    const float* head_b  = (const float*)d_in[21];

    int B = in_sizes[0] / SEQIN;

    TorrinE0_fused_kernel<<<B, NT>>>(
        x, conv_w, conv_b, cls_emb, Wqkv, bqkv, Wo, bo, W1, b1, W2, b2,
        ln1_g, ln1_b, ln2_g, ln2_b, lnf_g, lnf_b, end_w, end_b, head_w, head_b,
        (float*)d_out);
}

// round 4
// speedup vs baseline: 3.6262x; 1.6311x over previous
#include <cuda_runtime.h>
#include <cuda_bf16.h>

#define DD     16
#define NHEAD  8
#define LAYERS 8
#define FFD    16
#define KW     35
#define SEQIN  3500
#define NP     100
#define SS     101
#define HSTR   20      // padded row stride, 16B-aligned rows (20 floats = 80B)
#define NT     128     // threads per block
#define QB     8       // query rows per attention task
#define NBLK   13      // ceil(SS/QB)

__device__ __forceinline__ float ex2f_fast(float x) {
    float y;
    asm("ex2.approx.ftz.f32 %0, %1;" : "=f"(y) : "f"(x));
    return y;
}

// 16-element dot product via float4 (both pointers 16B aligned / register-promoted)
__device__ __forceinline__ float dot16(const float4* __restrict__ a,
                                       const float4* __restrict__ b, float acc) {
    #pragma unroll
    for (int i = 0; i < 4; i++) {
        float4 u = a[i], v = b[i];
        acc = fmaf(u.x, v.x, acc);
        acc = fmaf(u.y, v.y, acc);
        acc = fmaf(u.z, v.z, acc);
        acc = fmaf(u.w, v.w, acc);
    }
    return acc;
}

__global__ __launch_bounds__(NT, 5) void TorrinE0_fused_kernel(
    const float* __restrict__ x,      const float* __restrict__ conv_w, const float* __restrict__ conv_b,
    const float* __restrict__ cls_emb,const float* __restrict__ Wqkv,   const float* __restrict__ bqkv,
    const float* __restrict__ Wo,     const float* __restrict__ bo,
    const float* __restrict__ W1,     const float* __restrict__ b1,
    const float* __restrict__ W2,     const float* __restrict__ b2,
    const float* __restrict__ ln1_g,  const float* __restrict__ ln1_b,
    const float* __restrict__ ln2_g,  const float* __restrict__ ln2_b,
    const float* __restrict__ lnf_g,  const float* __restrict__ lnf_b,
    const float* __restrict__ end_w,  const float* __restrict__ end_b,
    const float* __restrict__ head_w, const float* __restrict__ head_b,
    float* __restrict__ out)
{
    __shared__ __align__(16) float s_h  [SS * HSTR];
    __shared__ __align__(16) float s_qkv[SS * 48];   // also holds x (3500 <= 4848) during conv
    __shared__ __align__(16) float s_ctx[SS * HSTR]; // attention output
    __shared__ __align__(16) float s_Wqkv[768];      // also holds conv_w (560) during conv
    __shared__ __align__(16) float s_bqkv[48];
    __shared__ __align__(16) float s_Wo[256], s_W1[256], s_W2[256];
    __shared__ float s_bo[16],  s_b1[16], s_b2[16];
    __shared__ float s_ln[64];                       // ln1_g, ln1_b, ln2_g, ln2_b

    const int tid = threadIdx.x;
    const int b   = blockIdx.x;

    // ---------- stage x row (float4) + conv weights ----------
    {
        const float4* x4 = reinterpret_cast<const float4*>(x + (size_t)b * SEQIN);
        float4* q4 = reinterpret_cast<float4*>(s_qkv);
        for (int i = tid; i < SEQIN / 4; i += NT) q4[i] = x4[i];
    }
    for (int i = tid; i < DD * KW; i += NT) s_Wqkv[i] = conv_w[i];
    if (tid < DD) s_bqkv[tid] = conv_b[tid];
    __syncthreads();

    // ---------- conv patch embedding: h[p+1][f] ----------
    for (int idx = tid; idx < NP * DD; idx += NT) {
        int p = idx >> 4, f = idx & 15;
        float acc = s_bqkv[f];
        const float* xp = &s_qkv[p * KW];
        const float* wf = &s_Wqkv[f * KW];
        #pragma unroll
        for (int k = 0; k < KW; k++) acc = fmaf(xp[k], wf[k], acc);
        s_h[(p + 1) * HSTR + f] = acc;
    }
    if (tid < DD) s_h[tid] = cls_emb[tid];
    __syncthreads();

    // fold softmax scale and log2(e) into q: exp(s*scale) == 2^(s*scale*log2e)
    const float QSC = 1.44269504088896f * 0.707106781186547f;

    // ---------- transformer layers ----------
    for (int l = 0; l < LAYERS; l++) {
        // stage this layer's weights into smem
        for (int i = tid; i < 768; i += NT) s_Wqkv[i] = Wqkv[l * 768 + i];
        for (int i = tid; i < 256; i += NT) {
            s_Wo[i] = Wo[l * 256 + i];
            s_W1[i] = W1[l * 256 + i];
            s_W2[i] = W2[l * 256 + i];
        }
        if (tid < 48) s_bqkv[tid] = bqkv[l * 48 + tid];
        if (tid < 16) {
            s_bo[tid]      = bo[l * 16 + tid];
            s_b1[tid]      = b1[l * 16 + tid];
            s_b2[tid]      = b2[l * 16 + tid];
            s_ln[tid]      = ln1_g[l * 16 + tid];
            s_ln[16 + tid] = ln1_b[l * 16 + tid];
            s_ln[32 + tid] = ln2_g[l * 16 + tid];
            s_ln[48 + tid] = ln2_b[l * 16 + tid];
        }
        __syncthreads();

        // ---- QKV projection: one row per thread, h in registers, weights broadcast ----
        if (tid < SS) {
            const float4* h4 = reinterpret_cast<const float4*>(&s_h[tid * HSTR]);
            float4 hr[4] = {h4[0], h4[1], h4[2], h4[3]};
            const float4* w4 = reinterpret_cast<const float4*>(s_Wqkv);
            float* qo = &s_qkv[tid * 48];
            #pragma unroll
            for (int e = 0; e < 48; e++)
                qo[e] = dot16(hr, w4 + e * 4, s_bqkv[e]);
        }
        __syncthreads();

        // ---- attention: single-pass softmax, QB query rows per task ----
        {
            const float2* qkv2 = reinterpret_cast<const float2*>(s_qkv);
            if (tid < NHEAD * NBLK) {
                int hh = tid / NBLK;
                int s0 = (tid - hh * NBLK) * QB;

                float2 q[QB];
                #pragma unroll
                for (int i = 0; i < QB; i++) {
                    int s = s0 + i;
                    if (s < SS) {
                        float2 t = qkv2[s * 24 + hh];
                        q[i].x = t.x * QSC; q[i].y = t.y * QSC;
                    } else {
                        q[i].x = 0.f; q[i].y = 0.f;
                    }
                }
                float den[QB], cx[QB], cy[QB];
                #pragma unroll
                for (int i = 0; i < QB; i++) { den[i] = 0.f; cx[i] = 0.f; cy[i] = 0.f; }

                for (int t = 0; t < SS; t++) {
                    float2 k = qkv2[t * 24 + 8  + hh];
                    float2 v = qkv2[t * 24 + 16 + hh];
                    #pragma unroll
                    for (int i = 0; i < QB; i++) {
                        float sc = fmaf(q[i].y, k.y, q[i].x * k.x);
                        float e  = ex2f_fast(sc);
                        den[i] += e;
                        cx[i] = fmaf(e, v.x, cx[i]);
                        cy[i] = fmaf(e, v.y, cy[i]);
                    }
                }
                #pragma unroll
                for (int i = 0; i < QB; i++) {
                    int s = s0 + i;
                    if (s < SS) {
                        float inv = __frcp_rn(den[i]);
                        float2 o; o.x = cx[i] * inv; o.y = cy[i] * inv;
                        *reinterpret_cast<float2*>(&s_ctx[s * HSTR + hh * 2]) = o;
                    }
                }
            }
        }
        __syncthreads();

        // ---- Wo + residual + LN1 + FF1 + FF2 + residual + LN2, fully per-row ----
        if (tid < SS) {
            const float4* c4 = reinterpret_cast<const float4*>(&s_ctx[tid * HSTR]);
            const float4* h4 = reinterpret_cast<const float4*>(&s_h[tid * HSTR]);
            float4 cr[4] = {c4[0], c4[1], c4[2], c4[3]};
            float4 hr4[4] = {h4[0], h4[1], h4[2], h4[3]};
            const float* hs = reinterpret_cast<const float*>(hr4);

            // Wo projection + residual
            const float4* wo4 = reinterpret_cast<const float4*>(s_Wo);
            float vv[16];
            float mu = 0.f;
            #pragma unroll
            for (int o = 0; o < 16; o++) {
                vv[o] = dot16(cr, wo4 + o * 4, s_bo[o]) + hs[o];
                mu += vv[o];
            }
            mu *= 0.0625f;
            float var = 0.f;
            #pragma unroll
            for (int d = 0; d < 16; d++) { float t = vv[d] - mu; var = fmaf(t, t, var); }
            float r = rsqrtf(fmaf(var, 0.0625f, 1e-5f));

            // LN1 result into registers (float4-typed for dot16)
            float4 ln1r[4];
            float* ln1s = reinterpret_cast<float*>(ln1r);
            #pragma unroll
            for (int d = 0; d < 16; d++)
                ln1s[d] = (vv[d] - mu) * r * s_ln[d] + s_ln[16 + d];

            // FF1 + relu, entirely in registers
            const float4* w14 = reinterpret_cast<const float4*>(s_W1);
            float4 fr[4];
            float* frs = reinterpret_cast<float*>(fr);
            #pragma unroll
            for (int f = 0; f < 16; f++)
                frs[f] = fmaxf(dot16(ln1r, w14 + f * 4, s_b1[f]), 0.f);

            // FF2 + residual + LN2
            const float4* w24 = reinterpret_cast<const float4*>(s_W2);
            mu = 0.f;
            #pragma unroll
            for (int d = 0; d < 16; d++) {
                vv[d] = dot16(fr, w24 + d * 4, s_b2[d]) + ln1s[d];
                mu += vv[d];
            }
            mu *= 0.0625f;
            var = 0.f;
            #pragma unroll
            for (int d = 0; d < 16; d++) { float t = vv[d] - mu; var = fmaf(t, t, var); }
            r = rsqrtf(fmaf(var, 0.0625f, 1e-5f));

            float4 ov[4];
            float* os = reinterpret_cast<float*>(ov);
            #pragma unroll
            for (int d = 0; d < 16; d++)
                os[d] = (vv[d] - mu) * r * s_ln[32 + d] + s_ln[48 + d];
            float4* oh = reinterpret_cast<float4*>(&s_h[tid * HSTR]);
            oh[0] = ov[0]; oh[1] = ov[1]; oh[2] = ov[2]; oh[3] = ov[3];
        }
        __syncthreads();
    }

    // ---------- final LN on cls row only ----------
    if (tid == 0) {
        float mu = 0.f;
        #pragma unroll
        for (int d = 0; d < 16; d++) mu += s_h[d];
        mu *= 0.0625f;
        float var = 0.f;
        #pragma unroll
        for (int d = 0; d < 16; d++) { float t = s_h[d] - mu; var = fmaf(t, t, var); }
        float r = rsqrtf(fmaf(var, 0.0625f, 1e-5f));
        #pragma unroll
        for (int d = 0; d < 16; d++)
            s_ctx[d] = (s_h[d] - mu) * r * lnf_g[d] + lnf_b[d];
    }
    __syncthreads();

    // ---------- end projection (fused with head weight) ----------
    if (tid < 100) {
        float acc = end_b[tid];
        #pragma unroll
        for (int d = 0; d < 16; d++) acc = fmaf(s_ctx[d], end_w[tid * 16 + d], acc);
        s_ctx[HSTR + tid] = acc * head_w[tid];   // park past the cls row
    }
    __syncthreads();

    // ---------- head sum + sigmoid ----------
    if (tid == 0) {
        float acc = head_b[0];
        #pragma unroll 4
        for (int j = 0; j < 100; j++) acc += s_ctx[HSTR + j];
        out[b] = 1.f / (1.f + ex2f_fast(-acc * 1.44269504088896f));
    }
}

extern "C" void kernel_launch(void* const* d_in, const int* in_sizes, int n_in,
                              void* d_out, int out_size) {
    const float* x       = (const float*)d_in[0];
    const float* conv_w  = (const float*)d_in[1];
    const float* conv_b  = (const float*)d_in[2];
    const float* cls_emb = (const float*)d_in[3];
    const float* Wqkv    = (const float*)d_in[4];
    const float* bqkv    = (const float*)d_in[5];
    const float* Wo      = (const float*)d_in[6];
    const float* bo      = (const float*)d_in[7];
    const float* W1      = (const float*)d_in[8];
    const float* b1      = (const float*)d_in[9];
    const float* W2      = (const float*)d_in[10];
    const float* b2      = (const float*)d_in[11];
    const float* ln1_g   = (const float*)d_in[12];
    const float* ln1_b   = (const float*)d_in[13];
    const float* ln2_g   = (const float*)d_in[14];
    const float* ln2_b   = (const float*)d_in[15];
    const float* lnf_g   = (const float*)d_in[16];
    const float* lnf_b   = (const float*)d_in[17];
    const float* end_w   = (const float*)d_in[18];
    const float* end_b   = (const float*)d_in[19];
    const float* head_w  = (const float*)d_in[20];
    const float* head_b  = (const float*)d_in[21];

    int B = in_sizes[0] / SEQIN;

    TorrinE0_fused_kernel<<<B, NT>>>(
        x, conv_w, conv_b, cls_emb, Wqkv, bqkv, Wo, bo, W1, b1, W2, b2,
        ln1_g, ln1_b, ln2_g, ln2_b, lnf_g, lnf_b, end_w, end_b, head_w, head_b,
        (float*)d_out);
}

// round 5
// speedup vs baseline: 3.7849x; 1.0438x over previous
#include <cuda_runtime.h>
#include <cuda_bf16.h>

#define DD     16
#define NHEAD  8
#define LAYERS 8
#define FFD    16
#define KW     35
#define SEQIN  3500
#define NP     100
#define SS     101
#define HSTR   20      // padded row stride for s_h / s_ctx
#define NT     128
#define QB     8       // query rows per attention task
#define NBLK   13      // ceil(SS/QB)

// s_att layout (floats): q rows [s][16] then transposed K/V per head
#define SQ_OFF 0
#define KX_OFF 1664
#define KY_OFF 2496
#define VX_OFF 3328
#define VY_OFF 4160
#define ATT_SZ 4992
#define TSTR   104     // per-head t stride (even -> 8B aligned pairs)

typedef unsigned long long u64;

__device__ __forceinline__ float ex2f_fast(float x) {
    float y;
    asm("ex2.approx.ftz.f32 %0, %1;" : "=f"(y) : "f"(x));
    return y;
}
__device__ __forceinline__ u64 pk2(float lo, float hi) {
    u64 r; asm("mov.b64 %0, {%1, %2};" : "=l"(r) : "f"(lo), "f"(hi)); return r;
}
__device__ __forceinline__ void upk2(u64 v, float& lo, float& hi) {
    asm("mov.b64 {%0, %1}, %2;" : "=f"(lo), "=f"(hi) : "l"(v));
}
__device__ __forceinline__ u64 fma2_(u64 a, u64 b, u64 c) {
    u64 r; asm("fma.rn.f32x2 %0, %1, %2, %3;" : "=l"(r) : "l"(a), "l"(b), "l"(c)); return r;
}
__device__ __forceinline__ u64 mul2_(u64 a, u64 b) {
    u64 r; asm("mul.rn.f32x2 %0, %1, %2;" : "=l"(r) : "l"(a), "l"(b)); return r;
}
__device__ __forceinline__ u64 add2_(u64 a, u64 b) {
    u64 r; asm("add.rn.f32x2 %0, %1, %2;" : "=l"(r) : "l"(a), "l"(b)); return r;
}

// packed 16-dot: a2 = 8 packed activation pairs (regs), w2 = smem weight row as u64*
__device__ __forceinline__ float dot16p(const u64* a2, const u64* __restrict__ w2, float bias) {
    u64 acc = pk2(bias, 0.f);
    #pragma unroll
    for (int j = 0; j < 8; j++) acc = fma2_(a2[j], w2[j], acc);
    float lo, hi; upk2(acc, lo, hi);
    return lo + hi;
}

__global__ __launch_bounds__(NT, 4) void TorrinE0_fused_kernel(
    const float* __restrict__ x,      const float* __restrict__ conv_w, const float* __restrict__ conv_b,
    const float* __restrict__ cls_emb,const float* __restrict__ Wqkv,   const float* __restrict__ bqkv,
    const float* __restrict__ Wo,     const float* __restrict__ bo,
    const float* __restrict__ W1,     const float* __restrict__ b1,
    const float* __restrict__ W2,     const float* __restrict__ b2,
    const float* __restrict__ ln1_g,  const float* __restrict__ ln1_b,
    const float* __restrict__ ln2_g,  const float* __restrict__ ln2_b,
    const float* __restrict__ lnf_g,  const float* __restrict__ lnf_b,
    const float* __restrict__ end_w,  const float* __restrict__ end_b,
    const float* __restrict__ head_w, const float* __restrict__ head_b,
    float* __restrict__ out)
{
    __shared__ __align__(16) float s_h  [SS * HSTR];
    __shared__ __align__(16) float s_att[ATT_SZ];    // q + transposed k/v; holds x during conv
    __shared__ __align__(16) float s_ctx[SS * HSTR];
    __shared__ __align__(16) float s_Wqkv[768];      // holds conv_w (560) during conv
    __shared__ __align__(16) float s_bqkv[48];
    __shared__ __align__(16) float s_Wo[256], s_W1[256], s_W2[256];
    __shared__ float s_bo[16],  s_b1[16], s_b2[16];
    __shared__ float s_ln[64];

    const int tid = threadIdx.x;
    const int b   = blockIdx.x;

    // ---------- stage x row + conv weights ----------
    {
        const float4* x4 = reinterpret_cast<const float4*>(x + (size_t)b * SEQIN);
        float4* q4 = reinterpret_cast<float4*>(s_att);
        for (int i = tid; i < SEQIN / 4; i += NT) q4[i] = x4[i];
    }
    for (int i = tid; i < DD * KW; i += NT) s_Wqkv[i] = conv_w[i];
    if (tid < DD) s_bqkv[tid] = conv_b[tid];
    __syncthreads();

    // ---------- conv patch embedding ----------
    for (int idx = tid; idx < NP * DD; idx += NT) {
        int p = idx >> 4, f = idx & 15;
        float acc = s_bqkv[f];
        const float* xp = &s_att[p * KW];
        const float* wf = &s_Wqkv[f * KW];
        #pragma unroll
        for (int k = 0; k < KW; k++) acc = fmaf(xp[k], wf[k], acc);
        s_h[(p + 1) * HSTR + f] = acc;
    }
    if (tid < DD) s_h[tid] = cls_emb[tid];
    __syncthreads();

    const float QSC = 1.44269504088896f * 0.707106781186547f; // log2e / sqrt(2)

    // ---------- transformer layers ----------
    for (int l = 0; l < LAYERS; l++) {
        for (int i = tid; i < 768; i += NT) s_Wqkv[i] = Wqkv[l * 768 + i];
        for (int i = tid; i < 256; i += NT) {
            s_Wo[i] = Wo[l * 256 + i];
            s_W1[i] = W1[l * 256 + i];
            s_W2[i] = W2[l * 256 + i];
        }
        if (tid < 48) s_bqkv[tid] = bqkv[l * 48 + tid];
        if (tid < 16) {
            s_bo[tid]      = bo[l * 16 + tid];
            s_b1[tid]      = b1[l * 16 + tid];
            s_b2[tid]      = b2[l * 16 + tid];
            s_ln[tid]      = ln1_g[l * 16 + tid];
            s_ln[16 + tid] = ln1_b[l * 16 + tid];
            s_ln[32 + tid] = ln2_g[l * 16 + tid];
            s_ln[48 + tid] = ln2_b[l * 16 + tid];
        }
        __syncthreads();

        // ---- QKV projection: h row in packed regs, weights broadcast LDS.64 ----
        if (tid < SS) {
            const float4* h4 = reinterpret_cast<const float4*>(&s_h[tid * HSTR]);
            float4 hr[4] = {h4[0], h4[1], h4[2], h4[3]};
            const float* hs = reinterpret_cast<const float*>(hr);
            u64 h2[8];
            #pragma unroll
            for (int j = 0; j < 8; j++) h2[j] = pk2(hs[2*j], hs[2*j+1]);
            const u64* w2 = reinterpret_cast<const u64*>(s_Wqkv);

            float* qrow = &s_att[SQ_OFF + tid * 16];
            #pragma unroll
            for (int e = 0; e < 16; e++)
                qrow[e] = dot16p(h2, w2 + e * 8, s_bqkv[e]);
            #pragma unroll
            for (int hh = 0; hh < NHEAD; hh++) {
                s_att[KX_OFF + hh * TSTR + tid] = dot16p(h2, w2 + (16 + 2*hh)     * 8, s_bqkv[16 + 2*hh]);
                s_att[KY_OFF + hh * TSTR + tid] = dot16p(h2, w2 + (16 + 2*hh + 1) * 8, s_bqkv[16 + 2*hh + 1]);
                s_att[VX_OFF + hh * TSTR + tid] = dot16p(h2, w2 + (32 + 2*hh)     * 8, s_bqkv[32 + 2*hh]);
                s_att[VY_OFF + hh * TSTR + tid] = dot16p(h2, w2 + (32 + 2*hh + 1) * 8, s_bqkv[32 + 2*hh + 1]);
            }
        }
        __syncthreads();

        // ---- attention: packed over t-pairs, single-pass softmax ----
        if (tid < NHEAD * NBLK) {
            int hh = tid / NBLK;
            int s0 = (tid - hh * NBLK) * QB;

            u64 qx2[QB], qy2[QB];
            #pragma unroll
            for (int i = 0; i < QB; i++) {
                int s = s0 + i;
                float qx = 0.f, qy = 0.f;
                if (s < SS) {
                    qx = s_att[SQ_OFF + s * 16 + 2*hh]     * QSC;
                    qy = s_att[SQ_OFF + s * 16 + 2*hh + 1] * QSC;
                }
                qx2[i] = pk2(qx, qx);
                qy2[i] = pk2(qy, qy);
            }
            u64 den2[QB], cx2[QB], cy2[QB];
            #pragma unroll
            for (int i = 0; i < QB; i++) { den2[i] = 0ull; cx2[i] = 0ull; cy2[i] = 0ull; }

            const u64* kxp = reinterpret_cast<const u64*>(&s_att[KX_OFF + hh * TSTR]);
            const u64* kyp = reinterpret_cast<const u64*>(&s_att[KY_OFF + hh * TSTR]);
            const u64* vxp = reinterpret_cast<const u64*>(&s_att[VX_OFF + hh * TSTR]);
            const u64* vyp = reinterpret_cast<const u64*>(&s_att[VY_OFF + hh * TSTR]);

            for (int tp = 0; tp < SS / 2; tp++) {   // 50 pairs covering t=0..99
                u64 kx2 = kxp[tp], ky2 = kyp[tp];
                u64 vx2 = vxp[tp], vy2 = vyp[tp];
                #pragma unroll
                for (int i = 0; i < QB; i++) {
                    u64 sc2 = fma2_(qy2[i], ky2, mul2_(qx2[i], kx2));
                    float sa, sb; upk2(sc2, sa, sb);
                    u64 e2 = pk2(ex2f_fast(sa), ex2f_fast(sb));
                    den2[i] = add2_(den2[i], e2);
                    cx2[i]  = fma2_(e2, vx2, cx2[i]);
                    cy2[i]  = fma2_(e2, vy2, cy2[i]);
                }
            }
            // tail t = 100
            float kxl = s_att[KX_OFF + hh * TSTR + SS - 1];
            float kyl = s_att[KY_OFF + hh * TSTR + SS - 1];
            float vxl = s_att[VX_OFF + hh * TSTR + SS - 1];
            float vyl = s_att[VY_OFF + hh * TSTR + SS - 1];

            #pragma unroll
            for (int i = 0; i < QB; i++) {
                int s = s0 + i;
                float d0, d1, a0, a1;
                upk2(den2[i], d0, d1); float den = d0 + d1;
                upk2(cx2[i],  a0, a1); float cx  = a0 + a1;
                upk2(cy2[i],  a0, a1); float cy  = a0 + a1;
                float qx, qdup, qy;
                upk2(qx2[i], qx, qdup);
                upk2(qy2[i], qy, qdup);
                float e = ex2f_fast(fmaf(qy, kyl, qx * kxl));
                den += e; cx = fmaf(e, vxl, cx); cy = fmaf(e, vyl, cy);
                if (s < SS) {
                    float inv = __frcp_rn(den);
                    float2 o; o.x = cx * inv; o.y = cy * inv;
                    *reinterpret_cast<float2*>(&s_ctx[s * HSTR + hh * 2]) = o;
                }
            }
        }
        __syncthreads();

        // ---- Wo + residual + LN1 + FF1 + FF2 + residual + LN2, per row, packed ----
        if (tid < SS) {
            const float4* c4 = reinterpret_cast<const float4*>(&s_ctx[tid * HSTR]);
            const float4* h4 = reinterpret_cast<const float4*>(&s_h[tid * HSTR]);
            float4 cr[4]  = {c4[0], c4[1], c4[2], c4[3]};
            float4 hr4[4] = {h4[0], h4[1], h4[2], h4[3]};
            const float* cs = reinterpret_cast<const float*>(cr);
            const float* hs = reinterpret_cast<const float*>(hr4);

            u64 c2[8];
            #pragma unroll
            for (int j = 0; j < 8; j++) c2[j] = pk2(cs[2*j], cs[2*j+1]);

            const u64* wo2 = reinterpret_cast<const u64*>(s_Wo);
            float vv[16];
            float mu = 0.f;
            #pragma unroll
            for (int o = 0; o < 16; o++) {
                vv[o] = dot16p(c2, wo2 + o * 8, s_bo[o]) + hs[o];
                mu += vv[o];
            }
            mu *= 0.0625f;
            float var = 0.f;
            #pragma unroll
            for (int d = 0; d < 16; d++) { float t = vv[d] - mu; var = fmaf(t, t, var); }
            float r = rsqrtf(fmaf(var, 0.0625f, 1e-5f));

            float ln1s[16];
            #pragma unroll
            for (int d = 0; d < 16; d++)
                ln1s[d] = (vv[d] - mu) * r * s_ln[d] + s_ln[16 + d];
            u64 l2[8];
            #pragma unroll
            for (int j = 0; j < 8; j++) l2[j] = pk2(ln1s[2*j], ln1s[2*j+1]);

            const u64* w12 = reinterpret_cast<const u64*>(s_W1);
            float frs[16];
            #pragma unroll
            for (int f = 0; f < 16; f++)
                frs[f] = fmaxf(dot16p(l2, w12 + f * 8, s_b1[f]), 0.f);
            u64 f2[8];
            #pragma unroll
            for (int j = 0; j < 8; j++) f2[j] = pk2(frs[2*j], frs[2*j+1]);

            const u64* w22 = reinterpret_cast<const u64*>(s_W2);
            mu = 0.f;
            #pragma unroll
            for (int d = 0; d < 16; d++) {
                vv[d] = dot16p(f2, w22 + d * 8, s_b2[d]) + ln1s[d];
                mu += vv[d];
            }
            mu *= 0.0625f;
            var = 0.f;
            #pragma unroll
            for (int d = 0; d < 16; d++) { float t = vv[d] - mu; var = fmaf(t, t, var); }
            r = rsqrtf(fmaf(var, 0.0625f, 1e-5f));

            float4 ov[4];
            float* os = reinterpret_cast<float*>(ov);
            #pragma unroll
            for (int d = 0; d < 16; d++)
                os[d] = (vv[d] - mu) * r * s_ln[32 + d] + s_ln[48 + d];
            float4* oh = reinterpret_cast<float4*>(&s_h[tid * HSTR]);
            oh[0] = ov[0]; oh[1] = ov[1]; oh[2] = ov[2]; oh[3] = ov[3];
        }
        __syncthreads();
    }

    // ---------- final LN (cls row) ----------
    if (tid == 0) {
        float mu = 0.f;
        #pragma unroll
        for (int d = 0; d < 16; d++) mu += s_h[d];
        mu *= 0.0625f;
        float var = 0.f;
        #pragma unroll
        for (int d = 0; d < 16; d++) { float t = s_h[d] - mu; var = fmaf(t, t, var); }
        float r = rsqrtf(fmaf(var, 0.0625f, 1e-5f));
        #pragma unroll
        for (int d = 0; d < 16; d++)
            s_ctx[d] = (s_h[d] - mu) * r * lnf_g[d] + lnf_b[d];
    }
    __syncthreads();

    // ---------- end projection (fused with head weight) ----------
    if (tid < 100) {
        float acc = end_b[tid];
        #pragma unroll
        for (int d = 0; d < 16; d++) acc = fmaf(s_ctx[d], end_w[tid * 16 + d], acc);
        s_ctx[HSTR + tid] = acc * head_w[tid];
    }
    __syncthreads();

    // ---------- head sum + sigmoid ----------
    if (tid == 0) {
        float acc = head_b[0];
        #pragma unroll 4
        for (int j = 0; j < 100; j++) acc += s_ctx[HSTR + j];
        out[b] = 1.f / (1.f + ex2f_fast(-acc * 1.44269504088896f));
    }
}

extern "C" void kernel_launch(void* const* d_in, const int* in_sizes, int n_in,
                              void* d_out, int out_size) {
    const float* x       = (const float*)d_in[0];
    const float* conv_w  = (const float*)d_in[1];
    const float* conv_b  = (const float*)d_in[2];
    const float* cls_emb = (const float*)d_in[3];
    const float* Wqkv    = (const float*)d_in[4];
    const float* bqkv    = (const float*)d_in[5];
    const float* Wo      = (const float*)d_in[6];
    const float* bo      = (const float*)d_in[7];
    const float* W1      = (const float*)d_in[8];
    const float* b1      = (const float*)d_in[9];
    const float* W2      = (const float*)d_in[10];
    const float* b2      = (const float*)d_in[11];
    const float* ln1_g   = (const float*)d_in[12];
    const float* ln1_b   = (const float*)d_in[13];
    const float* ln2_g   = (const float*)d_in[14];
    const float* ln2_b   = (const float*)d_in[15];
    const float* lnf_g   = (const float*)d_in[16];
    const float* lnf_b   = (const float*)d_in[17];
    const float* end_w   = (const float*)d_in[18];
    const float* end_b   = (const float*)d_in[19];
    const float* head_w  = (const float*)d_in[20];
    const float* head_b  = (const float*)d_in[21];

    int B = in_sizes[0] / SEQIN;

    TorrinE0_fused_kernel<<<B, NT>>>(
        x, conv_w, conv_b, cls_emb, Wqkv, bqkv, Wo, bo, W1, b1, W2, b2,
        ln1_g, ln1_b, ln2_g, ln2_b, lnf_g, lnf_b, end_w, end_b, head_w, head_b,
        (float*)d_out);
}

// round 6
// speedup vs baseline: 4.3124x; 1.1394x over previous
#include <cuda_runtime.h>
#include <cuda_bf16.h>

#define DD     16
#define NHEAD  8
#define LAYERS 8
#define FFD    16
#define KW     35
#define SEQIN  3500
#define NP     100
#define SS     101
#define HSTR   20      // padded row stride for s_h / s_ctx
#define NT     128
#define QB     7       // query rows per attention task
#define NBLK   15      // ceil(SS/QB) -> 8*15 = 120 tasks (<=128)

// s_att layout (floats): q rows [s][16] then transposed K/V per head
#define SQ_OFF 0
#define KX_OFF 1664
#define KY_OFF 2496
#define VX_OFF 3328
#define VY_OFF 4160
#define ATT_SZ 4992
#define TSTR   104     // per-head t stride (even -> 8B aligned pairs)

typedef unsigned long long u64;

__device__ __forceinline__ float ex2f_fast(float x) {
    float y;
    asm("ex2.approx.ftz.f32 %0, %1;" : "=f"(y) : "f"(x));
    return y;
}
__device__ __forceinline__ u64 pk2(float lo, float hi) {
    u64 r; asm("mov.b64 %0, {%1, %2};" : "=l"(r) : "f"(lo), "f"(hi)); return r;
}
__device__ __forceinline__ void upk2(u64 v, float& lo, float& hi) {
    asm("mov.b64 {%0, %1}, %2;" : "=f"(lo), "=f"(hi) : "l"(v));
}
__device__ __forceinline__ u64 fma2_(u64 a, u64 b, u64 c) {
    u64 r; asm("fma.rn.f32x2 %0, %1, %2, %3;" : "=l"(r) : "l"(a), "l"(b), "l"(c)); return r;
}
__device__ __forceinline__ u64 mul2_(u64 a, u64 b) {
    u64 r; asm("mul.rn.f32x2 %0, %1, %2;" : "=l"(r) : "l"(a), "l"(b)); return r;
}
__device__ __forceinline__ u64 add2_(u64 a, u64 b) {
    u64 r; asm("add.rn.f32x2 %0, %1, %2;" : "=l"(r) : "l"(a), "l"(b)); return r;
}

// packed 16-dot: a2 = 8 packed activation pairs (regs), w2 = smem weight row as u64*
__device__ __forceinline__ float dot16p(const u64* a2, const u64* __restrict__ w2, float bias) {
    u64 acc = pk2(bias, 0.f);
    #pragma unroll
    for (int j = 0; j < 8; j++) acc = fma2_(a2[j], w2[j], acc);
    float lo, hi; upk2(acc, lo, hi);
    return lo + hi;
}

__global__ __launch_bounds__(NT, 5) void TorrinE0_fused_kernel(
    const float* __restrict__ x,      const float* __restrict__ conv_w, const float* __restrict__ conv_b,
    const float* __restrict__ cls_emb,const float* __restrict__ Wqkv,   const float* __restrict__ bqkv,
    const float* __restrict__ Wo,     const float* __restrict__ bo,
    const float* __restrict__ W1,     const float* __restrict__ b1,
    const float* __restrict__ W2,     const float* __restrict__ b2,
    const float* __restrict__ ln1_g,  const float* __restrict__ ln1_b,
    const float* __restrict__ ln2_g,  const float* __restrict__ ln2_b,
    const float* __restrict__ lnf_g,  const float* __restrict__ lnf_b,
    const float* __restrict__ end_w,  const float* __restrict__ end_b,
    const float* __restrict__ head_w, const float* __restrict__ head_b,
    float* __restrict__ out)
{
    __shared__ __align__(16) float s_h  [SS * HSTR];
    __shared__ __align__(16) float s_att[ATT_SZ];    // q + transposed k/v; holds x during conv
    __shared__ __align__(16) float s_ctx[SS * HSTR];
    __shared__ __align__(16) float s_Wqkv[768];      // holds conv_w (560) during conv
    __shared__ __align__(16) float s_bqkv[48];
    __shared__ __align__(16) float s_Wo[256], s_W1[256], s_W2[256];
    __shared__ float s_bo[16],  s_b1[16], s_b2[16];
    __shared__ float s_ln[64];

    const int tid = threadIdx.x;
    const int b   = blockIdx.x;

    // ---------- stage x row + conv weights ----------
    {
        const float4* x4 = reinterpret_cast<const float4*>(x + (size_t)b * SEQIN);
        float4* q4 = reinterpret_cast<float4*>(s_att);
        for (int i = tid; i < SEQIN / 4; i += NT) q4[i] = x4[i];
    }
    for (int i = tid; i < DD * KW; i += NT) s_Wqkv[i] = conv_w[i];
    if (tid < DD) s_bqkv[tid] = conv_b[tid];
    __syncthreads();

    // ---------- conv patch embedding ----------
    for (int idx = tid; idx < NP * DD; idx += NT) {
        int p = idx >> 4, f = idx & 15;
        float acc = s_bqkv[f];
        const float* xp = &s_att[p * KW];
        const float* wf = &s_Wqkv[f * KW];
        #pragma unroll
        for (int k = 0; k < KW; k++) acc = fmaf(xp[k], wf[k], acc);
        s_h[(p + 1) * HSTR + f] = acc;
    }
    if (tid < DD) s_h[tid] = cls_emb[tid];
    __syncthreads();

    const float QSC = 1.44269504088896f * 0.707106781186547f; // log2e / sqrt(2)

    // ---------- transformer layers ----------
    for (int l = 0; l < LAYERS; l++) {
        for (int i = tid; i < 768; i += NT) s_Wqkv[i] = Wqkv[l * 768 + i];
        for (int i = tid; i < 256; i += NT) {
            s_Wo[i] = Wo[l * 256 + i];
            s_W1[i] = W1[l * 256 + i];
            s_W2[i] = W2[l * 256 + i];
        }
        if (tid < 48) s_bqkv[tid] = bqkv[l * 48 + tid];
        if (tid < 16) {
            s_bo[tid]      = bo[l * 16 + tid];
            s_b1[tid]      = b1[l * 16 + tid];
            s_b2[tid]      = b2[l * 16 + tid];
            s_ln[tid]      = ln1_g[l * 16 + tid];
            s_ln[16 + tid] = ln1_b[l * 16 + tid];
            s_ln[32 + tid] = ln2_g[l * 16 + tid];
            s_ln[48 + tid] = ln2_b[l * 16 + tid];
        }
        __syncthreads();

        // ---- QKV projection: h row in packed regs, weights broadcast LDS.64 ----
        if (tid < SS) {
            const float4* h4 = reinterpret_cast<const float4*>(&s_h[tid * HSTR]);
            float4 hr[4] = {h4[0], h4[1], h4[2], h4[3]};
            const float* hs = reinterpret_cast<const float*>(hr);
            u64 h2[8];
            #pragma unroll
            for (int j = 0; j < 8; j++) h2[j] = pk2(hs[2*j], hs[2*j+1]);
            const u64* w2 = reinterpret_cast<const u64*>(s_Wqkv);

            float* qrow = &s_att[SQ_OFF + tid * 16];
            #pragma unroll
            for (int e = 0; e < 16; e++)
                qrow[e] = dot16p(h2, w2 + e * 8, s_bqkv[e]);
            #pragma unroll
            for (int hh = 0; hh < NHEAD; hh++) {
                s_att[KX_OFF + hh * TSTR + tid] = dot16p(h2, w2 + (16 + 2*hh)     * 8, s_bqkv[16 + 2*hh]);
                s_att[KY_OFF + hh * TSTR + tid] = dot16p(h2, w2 + (16 + 2*hh + 1) * 8, s_bqkv[16 + 2*hh + 1]);
                s_att[VX_OFF + hh * TSTR + tid] = dot16p(h2, w2 + (32 + 2*hh)     * 8, s_bqkv[32 + 2*hh]);
                s_att[VY_OFF + hh * TSTR + tid] = dot16p(h2, w2 + (32 + 2*hh + 1) * 8, s_bqkv[32 + 2*hh + 1]);
            }
        }
        __syncthreads();

        // ---- attention: packed over t-pairs, single-pass softmax ----
        if (tid < NHEAD * NBLK) {
            int hh = tid / NBLK;
            int s0 = (tid - hh * NBLK) * QB;

            u64 qx2[QB], qy2[QB];
            #pragma unroll
            for (int i = 0; i < QB; i++) {
                int s = s0 + i;
                float qx = 0.f, qy = 0.f;
                if (s < SS) {
                    qx = s_att[SQ_OFF + s * 16 + 2*hh]     * QSC;
                    qy = s_att[SQ_OFF + s * 16 + 2*hh + 1] * QSC;
                }
                qx2[i] = pk2(qx, qx);
                qy2[i] = pk2(qy, qy);
            }
            u64 den2[QB], cx2[QB], cy2[QB];
            #pragma unroll
            for (int i = 0; i < QB; i++) { den2[i] = 0ull; cx2[i] = 0ull; cy2[i] = 0ull; }

            const u64* kxp = reinterpret_cast<const u64*>(&s_att[KX_OFF + hh * TSTR]);
            const u64* kyp = reinterpret_cast<const u64*>(&s_att[KY_OFF + hh * TSTR]);
            const u64* vxp = reinterpret_cast<const u64*>(&s_att[VX_OFF + hh * TSTR]);
            const u64* vyp = reinterpret_cast<const u64*>(&s_att[VY_OFF + hh * TSTR]);

            for (int tp = 0; tp < SS / 2; tp++) {   // 50 pairs covering t=0..99
                u64 kx2 = kxp[tp], ky2 = kyp[tp];
                u64 vx2 = vxp[tp], vy2 = vyp[tp];
                #pragma unroll
                for (int i = 0; i < QB; i++) {
                    u64 sc2 = fma2_(qy2[i], ky2, mul2_(qx2[i], kx2));
                    float sa, sb; upk2(sc2, sa, sb);
                    u64 e2 = pk2(ex2f_fast(sa), ex2f_fast(sb));
                    den2[i] = add2_(den2[i], e2);
                    cx2[i]  = fma2_(e2, vx2, cx2[i]);
                    cy2[i]  = fma2_(e2, vy2, cy2[i]);
                }
            }
            // tail t = 100
            float kxl = s_att[KX_OFF + hh * TSTR + SS - 1];
            float kyl = s_att[KY_OFF + hh * TSTR + SS - 1];
            float vxl = s_att[VX_OFF + hh * TSTR + SS - 1];
            float vyl = s_att[VY_OFF + hh * TSTR + SS - 1];

            #pragma unroll
            for (int i = 0; i < QB; i++) {
                int s = s0 + i;
                float d0, d1, a0, a1;
                upk2(den2[i], d0, d1); float den = d0 + d1;
                upk2(cx2[i],  a0, a1); float cx  = a0 + a1;
                upk2(cy2[i],  a0, a1); float cy  = a0 + a1;
                float qx, qdup, qy;
                upk2(qx2[i], qx, qdup);
                upk2(qy2[i], qy, qdup);
                float e = ex2f_fast(fmaf(qy, kyl, qx * kxl));
                den += e; cx = fmaf(e, vxl, cx); cy = fmaf(e, vyl, cy);
                if (s < SS) {
                    float inv = __frcp_rn(den);
                    float2 o; o.x = cx * inv; o.y = cy * inv;
                    *reinterpret_cast<float2*>(&s_ctx[s * HSTR + hh * 2]) = o;
                }
            }
        }
        __syncthreads();

        // ---- Wo + residual + LN1 + FF1 + FF2 + residual + LN2, per row, packed ----
        if (tid < SS) {
            const float4* c4 = reinterpret_cast<const float4*>(&s_ctx[tid * HSTR]);
            const float4* h4 = reinterpret_cast<const float4*>(&s_h[tid * HSTR]);
            float4 cr[4]  = {c4[0], c4[1], c4[2], c4[3]};
            float4 hr4[4] = {h4[0], h4[1], h4[2], h4[3]};
            const float* cs = reinterpret_cast<const float*>(cr);
            const float* hs = reinterpret_cast<const float*>(hr4);

            u64 c2[8];
            #pragma unroll
            for (int j = 0; j < 8; j++) c2[j] = pk2(cs[2*j], cs[2*j+1]);

            const u64* wo2 = reinterpret_cast<const u64*>(s_Wo);
            float vv[16];
            float mu = 0.f;
            #pragma unroll
            for (int o = 0; o < 16; o++) {
                vv[o] = dot16p(c2, wo2 + o * 8, s_bo[o]) + hs[o];
                mu += vv[o];
            }
            mu *= 0.0625f;
            float var = 0.f;
            #pragma unroll
            for (int d = 0; d < 16; d++) { float t = vv[d] - mu; var = fmaf(t, t, var); }
            float r = rsqrtf(fmaf(var, 0.0625f, 1e-5f));

            float ln1s[16];
            #pragma unroll
            for (int d = 0; d < 16; d++)
                ln1s[d] = (vv[d] - mu) * r * s_ln[d] + s_ln[16 + d];
            u64 l2[8];
            #pragma unroll
            for (int j = 0; j < 8; j++) l2[j] = pk2(ln1s[2*j], ln1s[2*j+1]);

            const u64* w12 = reinterpret_cast<const u64*>(s_W1);
            float frs[16];
            #pragma unroll
            for (int f = 0; f < 16; f++)
                frs[f] = fmaxf(dot16p(l2, w12 + f * 8, s_b1[f]), 0.f);
            u64 f2[8];
            #pragma unroll
            for (int j = 0; j < 8; j++) f2[j] = pk2(frs[2*j], frs[2*j+1]);

            const u64* w22 = reinterpret_cast<const u64*>(s_W2);
            mu = 0.f;
            #pragma unroll
            for (int d = 0; d < 16; d++) {
                vv[d] = dot16p(f2, w22 + d * 8, s_b2[d]) + ln1s[d];
                mu += vv[d];
            }
            mu *= 0.0625f;
            var = 0.f;
            #pragma unroll
            for (int d = 0; d < 16; d++) { float t = vv[d] - mu; var = fmaf(t, t, var); }
            r = rsqrtf(fmaf(var, 0.0625f, 1e-5f));

            float4 ov[4];
            float* os = reinterpret_cast<float*>(ov);
            #pragma unroll
            for (int d = 0; d < 16; d++)
                os[d] = (vv[d] - mu) * r * s_ln[32 + d] + s_ln[48 + d];
            float4* oh = reinterpret_cast<float4*>(&s_h[tid * HSTR]);
            oh[0] = ov[0]; oh[1] = ov[1]; oh[2] = ov[2]; oh[3] = ov[3];
        }
        __syncthreads();
    }

    // ---------- final LN (cls row) ----------
    if (tid == 0) {
        float mu = 0.f;
        #pragma unroll
        for (int d = 0; d < 16; d++) mu += s_h[d];
        mu *= 0.0625f;
        float var = 0.f;
        #pragma unroll
        for (int d = 0; d < 16; d++) { float t = s_h[d] - mu; var = fmaf(t, t, var); }
        float r = rsqrtf(fmaf(var, 0.0625f, 1e-5f));
        #pragma unroll
        for (int d = 0; d < 16; d++)
            s_ctx[d] = (s_h[d] - mu) * r * lnf_g[d] + lnf_b[d];
    }
    __syncthreads();

    // ---------- end projection (fused with head weight) ----------
    if (tid < 100) {
        float acc = end_b[tid];
        #pragma unroll
        for (int d = 0; d < 16; d++) acc = fmaf(s_ctx[d], end_w[tid * 16 + d], acc);
        s_ctx[HSTR + tid] = acc * head_w[tid];
    }
    __syncthreads();

    // ---------- head sum + sigmoid ----------
    if (tid == 0) {
        float acc = head_b[0];
        #pragma unroll 4
        for (int j = 0; j < 100; j++) acc += s_ctx[HSTR + j];
        out[b] = 1.f / (1.f + ex2f_fast(-acc * 1.44269504088896f));
    }
}

extern "C" void kernel_launch(void* const* d_in, const int* in_sizes, int n_in,
                              void* d_out, int out_size) {
    const float* x       = (const float*)d_in[0];
    const float* conv_w  = (const float*)d_in[1];
    const float* conv_b  = (const float*)d_in[2];
    const float* cls_emb = (const float*)d_in[3];
    const float* Wqkv    = (const float*)d_in[4];
    const float* bqkv    = (const float*)d_in[5];
    const float* Wo      = (const float*)d_in[6];
    const float* bo      = (const float*)d_in[7];
    const float* W1      = (const float*)d_in[8];
    const float* b1      = (const float*)d_in[9];
    const float* W2      = (const float*)d_in[10];
    const float* b2      = (const float*)d_in[11];
    const float* ln1_g   = (const float*)d_in[12];
    const float* ln1_b   = (const float*)d_in[13];
    const float* ln2_g   = (const float*)d_in[14];
    const float* ln2_b   = (const float*)d_in[15];
    const float* lnf_g   = (const float*)d_in[16];
    const float* lnf_b   = (const float*)d_in[17];
    const float* end_w   = (const float*)d_in[18];
    const float* end_b   = (const float*)d_in[19];
    const float* head_w  = (const float*)d_in[20];
    const float* head_b  = (const float*)d_in[21];

    int B = in_sizes[0] / SEQIN;

    TorrinE0_fused_kernel<<<B, NT>>>(
        x, conv_w, conv_b, cls_emb, Wqkv, bqkv, Wo, bo, W1, b1, W2, b2,
        ln1_g, ln1_b, ln2_g, ln2_b, lnf_g, lnf_b, end_w, end_b, head_w, head_b,
        (float*)d_out);
}